// round 16
// baseline (speedup 1.0000x reference)
#include <cuda_runtime.h>
#include <math.h>

#define BSZ 4

// ---------------- scratch (device globals; no allocations allowed) ----------
__device__ float g_v  [16777216];   // [4,64,256,256]
__device__ float g_x1d[ 4194304];   // [4,64,128,128]
__device__ float g_x2d[ 1572864];   // [4,96,64,64]
__device__ float g_xb [ 2097152];   // [4,128,64,64]
__device__ float g_x2c[14680064];   // [4,224,128,128] (x2 at coff 128)
__device__ float g_x2o[ 6291456];   // [4,96,128,128]
__device__ float g_x1c[41943040];   // [4,160,256,256] (x1 at coff 96)

__device__ float g_XW [ 3932160];   // transposed: [H][BC*m2c]
__device__ float g_XF [  368640];   // partial sums, K-part 0
__device__ float g_XF1[  368640];   // K-part 1
__device__ float g_XF2[  368640];   // K-part 2
__device__ float g_XF3[  368640];   // K-part 3
__device__ float g_OF [  368640];   // [B,Co,2m1,m2] complex
__device__ float g_Z  [ 1572864];   // [B,Co,H,m2] complex (scaled)
__device__ float g_tw [   26112];   // twiddle tables (complex interleaved)

#define TW0 0
#define TH0 3072
#define TW1 9216
#define TH1 10240
#define TW2 12288
#define TH2 12544

__device__ __forceinline__ float gelu_f(float x) {
    return 0.5f * x * (1.0f + erff(x * 0.70710678118654752f));
}

// ---------------- twiddle init -----------------------------------------------
__global__ void k_init_tw() {
    const int cfg[3][5] = {{256,12,12,TW0,TH0},{128,8,8,TW1,TH1},{64,4,4,TW2,TH2}};
    int tid = blockIdx.x * blockDim.x + threadIdx.x;
    int nth = gridDim.x * blockDim.x;
    for (int c = 0; c < 3; c++) {
        int H = cfg[c][0], m1 = cfg[c][1], m2 = cfg[c][2];
        int offW = cfg[c][3], offH = cfg[c][4];
        int nW = H * m2;
        for (int e = tid; e < nW; e += nth) {
            int w = e / m2, kw = e % m2;
            int p = (w * kw) % H;
            double s, co; sincos(2.0 * 3.14159265358979323846 * (double)p / (double)H, &s, &co);
            g_tw[(offW + e) * 2]     = (float)co;
            g_tw[(offW + e) * 2 + 1] = (float)(-s);
        }
        int m1t2 = 2 * m1;
        int nH = H * m1t2;
        for (int e = tid; e < nH; e += nth) {
            int h = e / m1t2, j = e % m1t2;
            int kh = (j < m1) ? j : (H - 2 * m1 + j);
            int p = (kh * h) % H;
            double s, co; sincos(2.0 * 3.14159265358979323846 * (double)p / (double)H, &s, &co);
            g_tw[(offH + e) * 2]     = (float)co;
            g_tw[(offH + e) * 2 + 1] = (float)(-s);
        }
    }
}

// ---------------- lift: tiled 64px x 64c -------------------------------------
__global__ void k_lift(const float* __restrict__ x, const float* __restrict__ w,
                       const float* __restrict__ bb) {
    __shared__ float xs6[64][8];
    __shared__ float ws6[64][8];
    const int HW = 256 * 256;
    int b  = blockIdx.x >> 10;
    int p0 = (blockIdx.x & 1023) << 6;
    int tid = threadIdx.x;

    const float* xp = x + ((size_t)b * HW + p0) * 6;
    for (int l = tid; l < 384; l += 256) xs6[l / 6][l % 6] = xp[l];
    for (int l = tid; l < 384; l += 256) ws6[l / 6][l % 6] = w[l];
    __syncthreads();

    int ty = tid >> 4, tx = tid & 15;
    #pragma unroll
    for (int cr = 0; cr < 4; cr++) {
        int c = ty * 4 + cr;
        float bias = bb[c];
        float res[4];
        #pragma unroll
        for (int pc = 0; pc < 4; pc++) {
            int p = tx * 4 + pc;
            float acc = bias;
            #pragma unroll
            for (int k = 0; k < 6; k++) acc += ws6[c][k] * xs6[p][k];
            res[pc] = acc;
        }
        *(float4*)(g_v + (size_t)(b * 64 + c) * HW + p0 + tx * 4) =
            make_float4(res[0], res[1], res[2], res[3]);
    }
}

// ------- fwd DFT along W with real-input symmetry ----------------------------
__global__ void k_fwd_w(const float* __restrict__ xin, int H, int W, int m2,
                        const float* __restrict__ tw, int BC) {
    __shared__ float raw[32][260];
    __shared__ float tws[129][25];
    int m2c = 2 * m2;
    int Wh = W >> 1;
    int r0 = blockIdx.x * 32;
    int tid = threadIdx.x;
    int row_l = tid >> 3;
    int kc0 = tid & 7;
    bool odd = (kc0 & 1);
    bool v1 = (kc0 + 8 < m2c), v2 = (kc0 + 16 < m2c);

    int nf4 = W >> 2;
    for (int l = tid; l < 32 * nf4; l += 256) {
        int r = l / nf4, q = (l % nf4) * 4;
        *(float4*)&raw[r][q] = *(const float4*)(xin + (size_t)(r0 + r) * W + q);
    }
    for (int l = tid; l < (Wh + 1) * m2c; l += 256) {
        int w = l / m2c, kc = l % m2c;
        tws[w][kc] = tw[(size_t)w * m2c + kc];
    }
    __syncthreads();

    for (int l = tid; l < 32 * (Wh - 1); l += 256) {
        int r = l / (Wh - 1), w = 1 + l % (Wh - 1);
        float a = raw[r][w], bv = raw[r][W - w];
        raw[r][w]     = a + bv;
        raw[r][W - w] = a - bv;
    }
    __syncthreads();

    float a0, a1 = 0.f, a2 = 0.f;
    {
        float x0 = raw[row_l][0], xh = raw[row_l][Wh];
        a0 = x0 * tws[0][kc0] + xh * tws[Wh][kc0];
        if (v1) a1 = x0 * tws[0][kc0 + 8]  + xh * tws[Wh][kc0 + 8];
        if (v2) a2 = x0 * tws[0][kc0 + 16] + xh * tws[Wh][kc0 + 16];
    }
    const float* rrow = raw[row_l];
    #pragma unroll 4
    for (int w = 1; w < Wh; w++) {
        float xv = rrow[odd ? (W - w) : w];
        a0 += xv * tws[w][kc0];
        if (v1) a1 += xv * tws[w][kc0 + 8];
        if (v2) a2 += xv * tws[w][kc0 + 16];
    }
    int r = r0 + row_l;
    int bc = r / H, h = r - bc * H;
    size_t base = ((size_t)h * BC + bc) * m2c;
    g_XW[base + kc0] = a0;
    if (v1) g_XW[base + kc0 + 8]  = a1;
    if (v2) g_XW[base + kc0 + 16] = a2;
}

// ------- fwd DFT along H: split-K over blockIdx.y (up to 4 parts) ------------
__global__ void k_fwd_h(int H, int H2, int BCm2, int m1, int m2,
                        const float* __restrict__ tw) {
    __shared__ float xs[64][32];
    __shared__ float tws[64][48];
    int m1t2 = 2 * m1;
    int cc0 = blockIdx.x * 16;
    int hy  = blockIdx.y;
    int hbeg = hy * H2, hend = hbeg + H2;
    int tid = threadIdx.x;
    int cl = tid & 15;
    int g  = tid >> 4;
    bool v0 = (g < m1t2);
    bool v1 = (g + 16 < m1t2);
    float ar0 = 0.f, ai0 = 0.f, ar1 = 0.f, ai1 = 0.f;
    int N2 = BCm2 * 2;

    for (int h0 = hbeg; h0 < hend; h0 += 64) {
        for (int l = tid; l < 64 * 8; l += 256) {
            int hh = l >> 3, c4 = (l & 7) * 4;
            *(float4*)&xs[hh][c4] =
                *(const float4*)(g_XW + (size_t)(h0 + hh) * N2 + cc0 * 2 + c4);
        }
        for (int l = tid; l < 64 * m1t2 * 2; l += 256) {
            int hh = l / (m1t2 * 2), c = l % (m1t2 * 2);
            tws[hh][c] = tw[(size_t)(h0 + hh) * m1t2 * 2 + c];
        }
        __syncthreads();
        #pragma unroll 4
        for (int hh = 0; hh < 64; hh++) {
            float2 xv = *(const float2*)&xs[hh][2 * cl];
            if (v0) {
                float tr = tws[hh][2 * g], ti = tws[hh][2 * g + 1];
                ar0 += xv.x * tr - xv.y * ti;
                ai0 += xv.x * ti + xv.y * tr;
            }
            if (v1) {
                float tr1 = tws[hh][2 * (g + 16)], ti1 = tws[hh][2 * (g + 16) + 1];
                ar1 += xv.x * tr1 - xv.y * ti1;
                ai1 += xv.x * ti1 + xv.y * tr1;
            }
        }
        __syncthreads();
    }
    float* dst = (hy == 0) ? g_XF : (hy == 1) ? g_XF1 : (hy == 2) ? g_XF2 : g_XF3;
    int cc = cc0 + cl, bc = cc / m2, kw = cc % m2;
    if (v0) {
        size_t oo = (((size_t)bc * m1t2 + g) * m2 + kw) * 2;
        dst[oo] = ar0; dst[oo + 1] = ai0;
    }
    if (v1) {
        size_t oo = (((size_t)bc * m1t2 + g + 16) * m2 + kw) * 2;
        dst[oo] = ar1; dst[oo + 1] = ai1;
    }
}

// ------- per-mode channel mix; sums split-K partials during staging ----------
__global__ void k_mix(int Ci, int Co, int m1, int m2, int nparts,
                      const float* __restrict__ w1, const float* __restrict__ w2) {
    __shared__ float xf_s[3840];
    int m1t2 = 2 * m1, m2c = 2 * m2;
    int kk = blockIdx.x % m1t2;
    int b  = blockIdx.x / m1t2;
    int oy = blockIdx.y;
    int tid = threadIdx.x;

    for (int l = tid; l < Ci * m2c; l += 256) {
        int i = l / m2c, kc = l % m2c;
        size_t gi = (((size_t)(b * Ci + i) * m1t2 + kk) * m2) * 2 + kc;
        float v = g_XF[gi];
        if (nparts >= 2) v += g_XF1[gi];
        if (nparts >= 4) v += g_XF2[gi] + g_XF3[gi];
        xf_s[l] = v;
    }
    __syncthreads();

    int kkr = (kk < m1) ? kk : kk - m1;
    const float* wsel = (kk < m1) ? w1 : w2;
    int wstride = Co * m1 * m2 * 2;
    int nout = Co * m2;
    int half = nout >> 1;
    int e_begin = oy * half;
    int e_end   = e_begin + half;
    for (int e0 = e_begin + tid; e0 < e_end; e0 += 1024) {
        float orr[4] = {0,0,0,0}, oii[4] = {0,0,0,0};
        int xoff[4], woff[4]; bool val[4];
        #pragma unroll
        for (int u = 0; u < 4; u++) {
            int e = e0 + 256 * u;
            val[u] = (e < e_end);
            int kw = val[u] ? e % m2 : 0;
            int o  = val[u] ? e / m2 : 0;
            xoff[u] = 2 * kw;
            woff[u] = ((o * m1 + kkr) * m2 + kw) * 2;
        }
        for (int i = 0; i < Ci; i++) {
            const float* wrow = wsel + (size_t)i * wstride;
            const float* xrow = xf_s + i * m2c;
            #pragma unroll
            for (int u = 0; u < 4; u++) {
                float xr = xrow[xoff[u]], xi = xrow[xoff[u] + 1];
                float wr = wrow[woff[u]], wi = wrow[woff[u] + 1];
                orr[u] += xr * wr - xi * wi;
                oii[u] += xr * wi + xi * wr;
            }
        }
        #pragma unroll
        for (int u = 0; u < 4; u++) {
            if (val[u]) {
                int e = e0 + 256 * u;
                int kw = e % m2, o = e / m2;
                size_t oo = (((size_t)(b * Co + o) * m1t2 + kk) * m2 + kw) * 2;
                g_OF[oo] = orr[u]; g_OF[oo + 1] = oii[u];
            }
        }
    }
}

// ------- inverse DFT along H; H rows split over blockIdx.y (ny parts) --------
__global__ void k_inv_h(int H, int m1, int m2, const float* __restrict__ tw,
                        float invHW, int ny) {
    __shared__ float of_s[1152];
    int bo = blockIdx.x;
    int hy = blockIdx.y;
    int tid = threadIdx.x;
    int m1t2 = 2 * m1;
    int nload = m1t2 * m2 * 2;
    const float* src = g_OF + (size_t)bo * nload;
    for (int l = tid; l < nload; l += 256) of_s[l] = src[l];
    __syncthreads();

    int nout = H * m2;
    int nh = nout / ny;
    int e_begin = hy * nh;
    int e_end = e_begin + nh;
    for (int e = e_begin + tid; e < e_end; e += 512) {
        int e2 = e + 256;
        bool v2 = (e2 < e_end);
        int kw0 = e % m2, h0 = e / m2;
        int kw1 = v2 ? e2 % m2 : 0, h1 = v2 ? e2 / m2 : 0;
        float zr0 = 0.f, zi0 = 0.f, zr1 = 0.f, zi1 = 0.f;
        for (int kk = 0; kk < m1t2; kk++) {
            float tr0 = tw[(h0 * m1t2 + kk) * 2], ti0 = tw[(h0 * m1t2 + kk) * 2 + 1];
            float fr0 = of_s[(kk * m2 + kw0) * 2], fi0 = of_s[(kk * m2 + kw0) * 2 + 1];
            zr0 += fr0 * tr0 + fi0 * ti0;
            zi0 += fi0 * tr0 - fr0 * ti0;
            float tr1 = tw[(h1 * m1t2 + kk) * 2], ti1 = tw[(h1 * m1t2 + kk) * 2 + 1];
            float fr1 = of_s[(kk * m2 + kw1) * 2], fi1 = of_s[(kk * m2 + kw1) * 2 + 1];
            zr1 += fr1 * tr1 + fi1 * ti1;
            zi1 += fi1 * tr1 - fr1 * ti1;
        }
        size_t oo = ((size_t)bo * nout + e) * 2;
        g_Z[oo] = zr0 * invHW; g_Z[oo + 1] = zi0 * invHW;
        if (v2) {
            oo = ((size_t)bo * nout + e2) * 2;
            g_Z[oo] = zr1 * invHW; g_Z[oo + 1] = zi1 * invHW;
        }
    }
}

// ------- fused GEMM: ping-pong smem double buffering, one sync per K-chunk ---
__global__ void k_fuse(const float* __restrict__ xin, int Ci, int Co,
                       int H, int W, int m2, const float* __restrict__ tw,
                       const float* __restrict__ cw, const float* __restrict__ cb,
                       float* __restrict__ out, int Ct, int coff) {
    __shared__ float xs[2][32][68];
    __shared__ float wst[2][32][68];
    __shared__ float zst[24][68];
    __shared__ float twst[24][68];

    const int HW = H * W;
    int tilesPerImg = HW >> 6;
    int b  = blockIdx.x / tilesPerImg;
    int p0 = (blockIdx.x % tilesPerImg) << 6;
    int ob = blockIdx.y << 6;
    int h  = p0 / W, w0 = p0 % W;
    int tid = threadIdx.x;
    int ty = tid >> 4, tx = tid & 15;
    int m2c = 2 * m2;

    int l0 = tid, l1 = tid + 256;
    int xi0 = l0 >> 4, xq0 = (l0 & 15) * 4;
    int xi1 = l1 >> 4, xq1 = (l1 & 15) * 4;
    int wo0 = l0 >> 3, wj0 = (l0 & 7) * 4;
    int wo1 = l1 >> 3, wj1 = (l1 & 7) * 4;
    int woo0 = ob + wo0, woo1 = ob + wo1;
    const float* wrow0 = cw + (size_t)woo0 * Ci;
    const float* wrow1 = cw + (size_t)woo1 * Ci;
    bool wv0 = (woo0 < Co), wv1 = (woo1 < Co);

    for (int l = tid; l < m2c * 64; l += 256) {
        int r = l >> 6, o = l & 63;
        int oo = ob + o;
        float v = (oo < Co) ? g_Z[(((size_t)(b * Co + oo) * H + h) * m2) * 2 + r] : 0.f;
        zst[r][o] = (r >= 2) ? 2.0f * v : v;
    }
    for (int l = tid; l < m2c * 64; l += 256) {
        int r = l >> 6, p = l & 63;
        twst[r][p] = tw[(size_t)(w0 + p) * m2c + r];
    }
    {
        float4 xa = *(const float4*)(xin + (size_t)(b * Ci + xi0) * HW + p0 + xq0);
        float4 xb = *(const float4*)(xin + (size_t)(b * Ci + xi1) * HW + p0 + xq1);
        float4 wa = wv0 ? *(const float4*)(wrow0 + wj0) : make_float4(0.f,0.f,0.f,0.f);
        float4 wb = wv1 ? *(const float4*)(wrow1 + wj1) : make_float4(0.f,0.f,0.f,0.f);
        *(float4*)&xs[0][xi0][xq0] = xa;
        *(float4*)&xs[0][xi1][xq1] = xb;
        wst[0][wj0][wo0] = wa.x; wst[0][wj0+1][wo0] = wa.y;
        wst[0][wj0+2][wo0] = wa.z; wst[0][wj0+3][wo0] = wa.w;
        wst[0][wj1][wo1] = wb.x; wst[0][wj1+1][wo1] = wb.y;
        wst[0][wj1+2][wo1] = wb.z; wst[0][wj1+3][wo1] = wb.w;
    }
    __syncthreads();

    float acc[4][4];
    #pragma unroll
    for (int r = 0; r < 4; r++)
        #pragma unroll
        for (int c = 0; c < 4; c++) acc[r][c] = 0.f;
    for (int r = 0; r < m2c; r++) {
        float4 zv = *(const float4*)&zst[r][ty * 4];
        float4 tv = *(const float4*)&twst[r][tx * 4];
        acc[0][0] += zv.x * tv.x; acc[0][1] += zv.x * tv.y;
        acc[0][2] += zv.x * tv.z; acc[0][3] += zv.x * tv.w;
        acc[1][0] += zv.y * tv.x; acc[1][1] += zv.y * tv.y;
        acc[1][2] += zv.y * tv.z; acc[1][3] += zv.y * tv.w;
        acc[2][0] += zv.z * tv.x; acc[2][1] += zv.z * tv.y;
        acc[2][2] += zv.z * tv.z; acc[2][3] += zv.z * tv.w;
        acc[3][0] += zv.w * tv.x; acc[3][1] += zv.w * tv.y;
        acc[3][2] += zv.w * tv.z; acc[3][3] += zv.w * tv.w;
    }

    int nchunks = Ci >> 5;
    for (int k = 0; k < nchunks; k++) {
        int cur = k & 1;
        bool more = (k + 1 < nchunks);
        float4 xa, xb, wa, wb;
        if (more) {
            int cin = (k + 1) << 5;
            xa = *(const float4*)(xin + (size_t)(b * Ci + cin + xi0) * HW + p0 + xq0);
            xb = *(const float4*)(xin + (size_t)(b * Ci + cin + xi1) * HW + p0 + xq1);
            wa = wv0 ? *(const float4*)(wrow0 + cin + wj0) : make_float4(0.f,0.f,0.f,0.f);
            wb = wv1 ? *(const float4*)(wrow1 + cin + wj1) : make_float4(0.f,0.f,0.f,0.f);
        }
        #pragma unroll
        for (int i = 0; i < 32; i++) {
            float4 xv = *(const float4*)&xs[cur][i][tx * 4];
            float4 wv = *(const float4*)&wst[cur][i][ty * 4];
            acc[0][0] += wv.x * xv.x; acc[0][1] += wv.x * xv.y;
            acc[0][2] += wv.x * xv.z; acc[0][3] += wv.x * xv.w;
            acc[1][0] += wv.y * xv.x; acc[1][1] += wv.y * xv.y;
            acc[1][2] += wv.y * xv.z; acc[1][3] += wv.y * xv.w;
            acc[2][0] += wv.z * xv.x; acc[2][1] += wv.z * xv.y;
            acc[2][2] += wv.z * xv.z; acc[2][3] += wv.z * xv.w;
            acc[3][0] += wv.w * xv.x; acc[3][1] += wv.w * xv.y;
            acc[3][2] += wv.w * xv.z; acc[3][3] += wv.w * xv.w;
        }
        if (more) {
            int nb = cur ^ 1;
            *(float4*)&xs[nb][xi0][xq0] = xa;
            *(float4*)&xs[nb][xi1][xq1] = xb;
            wst[nb][wj0][wo0] = wa.x; wst[nb][wj0+1][wo0] = wa.y;
            wst[nb][wj0+2][wo0] = wa.z; wst[nb][wj0+3][wo0] = wa.w;
            wst[nb][wj1][wo1] = wb.x; wst[nb][wj1+1][wo1] = wb.y;
            wst[nb][wj1+2][wo1] = wb.z; wst[nb][wj1+3][wo1] = wb.w;
            __syncthreads();
        }
    }

    #pragma unroll
    for (int r = 0; r < 4; r++) {
        int oo = ob + ty * 4 + r;
        if (oo >= Co) continue;
        float bias = cb[oo];
        float res[4];
        #pragma unroll
        for (int c = 0; c < 4; c++) res[c] = gelu_f(acc[r][c] + bias);
        *(float4*)(out + (size_t)(b * Ct + coff + oo) * HW + p0 + tx * 4) =
            make_float4(res[0], res[1], res[2], res[3]);
    }
}

// ------- FINAL LAYER: fuse(su1) + head merged; x1o never touches gmem --------
__global__ void k_fuse_head(const float* __restrict__ xin, int Ci,
                            const float* __restrict__ tw,
                            const float* __restrict__ cw, const float* __restrict__ cb,
                            const float* __restrict__ w1, const float* __restrict__ b1,
                            const float* __restrict__ w2, const float* __restrict__ b2,
                            float* __restrict__ out) {
    __shared__ float S[11968];
    #define A_XS(bf,i,q)  S[(bf) * 2176 + (i) * 68 + (q)]
    #define A_WS(bf,i,o)  S[4352 + (bf) * 2176 + (i) * 68 + (o)]
    #define A_ZS(r,o)     S[8704 + (r) * 68 + (o)]
    #define A_TW(r,p)     S[10336 + (r) * 68 + (p)]
    #define B_X(i,p)      S[(i) * 68 + (p)]
    #define B_W(i,o)      S[4352 + (i) * 68 + (o)]
    #define B_R(t,l)      S[8704 + (t) * 200 + (l)]

    const int H = 256, m2 = 12, m2c = 24;
    const int HW = 65536;
    int b  = blockIdx.x >> 10;
    int p0 = (blockIdx.x & 1023) << 6;
    int h  = p0 >> 8, w0 = p0 & 255;
    int tid = threadIdx.x;
    int ty = tid >> 4, tx = tid & 15;

    int l0 = tid, l1 = tid + 256;
    int xi0 = l0 >> 4, xq0 = (l0 & 15) * 4;
    int xi1 = l1 >> 4, xq1 = (l1 & 15) * 4;
    int wo0 = l0 >> 3, wj0 = (l0 & 7) * 4;
    int wo1 = l1 >> 3, wj1 = (l1 & 7) * 4;
    const float* wrow0 = cw + (size_t)wo0 * Ci;
    const float* wrow1 = cw + (size_t)wo1 * Ci;

    for (int l = tid; l < m2c * 64; l += 256) {
        int r = l >> 6, o = l & 63;
        float v = g_Z[(((size_t)(b * 64 + o) * H + h) * m2) * 2 + r];
        A_ZS(r, o) = (r >= 2) ? 2.0f * v : v;
    }
    for (int l = tid; l < m2c * 64; l += 256) {
        int r = l >> 6, p = l & 63;
        A_TW(r, p) = tw[(size_t)(w0 + p) * m2c + r];
    }
    {
        float4 xa = *(const float4*)(xin + (size_t)(b * Ci + xi0) * HW + p0 + xq0);
        float4 xb = *(const float4*)(xin + (size_t)(b * Ci + xi1) * HW + p0 + xq1);
        float4 wa = *(const float4*)(wrow0 + wj0);
        float4 wb = *(const float4*)(wrow1 + wj1);
        *(float4*)&A_XS(0, xi0, xq0) = xa;
        *(float4*)&A_XS(0, xi1, xq1) = xb;
        A_WS(0, wj0, wo0) = wa.x; A_WS(0, wj0+1, wo0) = wa.y;
        A_WS(0, wj0+2, wo0) = wa.z; A_WS(0, wj0+3, wo0) = wa.w;
        A_WS(0, wj1, wo1) = wb.x; A_WS(0, wj1+1, wo1) = wb.y;
        A_WS(0, wj1+2, wo1) = wb.z; A_WS(0, wj1+3, wo1) = wb.w;
    }
    __syncthreads();

    float acc[4][4];
    #pragma unroll
    for (int r = 0; r < 4; r++)
        #pragma unroll
        for (int c = 0; c < 4; c++) acc[r][c] = 0.f;
    for (int r = 0; r < m2c; r++) {
        float4 zv = *(const float4*)&A_ZS(r, ty * 4);
        float4 tv = *(const float4*)&A_TW(r, tx * 4);
        acc[0][0] += zv.x * tv.x; acc[0][1] += zv.x * tv.y;
        acc[0][2] += zv.x * tv.z; acc[0][3] += zv.x * tv.w;
        acc[1][0] += zv.y * tv.x; acc[1][1] += zv.y * tv.y;
        acc[1][2] += zv.y * tv.z; acc[1][3] += zv.y * tv.w;
        acc[2][0] += zv.z * tv.x; acc[2][1] += zv.z * tv.y;
        acc[2][2] += zv.z * tv.z; acc[2][3] += zv.z * tv.w;
        acc[3][0] += zv.w * tv.x; acc[3][1] += zv.w * tv.y;
        acc[3][2] += zv.w * tv.z; acc[3][3] += zv.w * tv.w;
    }

    int nchunks = Ci >> 5;
    for (int k = 0; k < nchunks; k++) {
        int cur = k & 1;
        bool more = (k + 1 < nchunks);
        float4 xa, xb, wa, wb;
        if (more) {
            int cin = (k + 1) << 5;
            xa = *(const float4*)(xin + (size_t)(b * Ci + cin + xi0) * HW + p0 + xq0);
            xb = *(const float4*)(xin + (size_t)(b * Ci + cin + xi1) * HW + p0 + xq1);
            wa = *(const float4*)(wrow0 + cin + wj0);
            wb = *(const float4*)(wrow1 + cin + wj1);
        }
        #pragma unroll
        for (int i = 0; i < 32; i++) {
            float4 xv = *(const float4*)&A_XS(cur, i, tx * 4);
            float4 wv = *(const float4*)&A_WS(cur, i, ty * 4);
            acc[0][0] += wv.x * xv.x; acc[0][1] += wv.x * xv.y;
            acc[0][2] += wv.x * xv.z; acc[0][3] += wv.x * xv.w;
            acc[1][0] += wv.y * xv.x; acc[1][1] += wv.y * xv.y;
            acc[1][2] += wv.y * xv.z; acc[1][3] += wv.y * xv.w;
            acc[2][0] += wv.z * xv.x; acc[2][1] += wv.z * xv.y;
            acc[2][2] += wv.z * xv.z; acc[2][3] += wv.z * xv.w;
            acc[3][0] += wv.w * xv.x; acc[3][1] += wv.w * xv.y;
            acc[3][2] += wv.w * xv.z; acc[3][3] += wv.w * xv.w;
        }
        if (more) {
            int nb = cur ^ 1;
            *(float4*)&A_XS(nb, xi0, xq0) = xa;
            *(float4*)&A_XS(nb, xi1, xq1) = xb;
            A_WS(nb, wj0, wo0) = wa.x; A_WS(nb, wj0+1, wo0) = wa.y;
            A_WS(nb, wj0+2, wo0) = wa.z; A_WS(nb, wj0+3, wo0) = wa.w;
            A_WS(nb, wj1, wo1) = wb.x; A_WS(nb, wj1+1, wo1) = wb.y;
            A_WS(nb, wj1+2, wo1) = wb.z; A_WS(nb, wj1+3, wo1) = wb.w;
            __syncthreads();
        }
    }
    __syncthreads();   // all reads of phase-A buffers done before overwrite

    // write x1o tile into B_X region
    #pragma unroll
    for (int r = 0; r < 4; r++) {
        int oo = ty * 4 + r;
        float bias = cb[oo];
        float4 rv;
        rv.x = gelu_f(acc[r][0] + bias);
        rv.y = gelu_f(acc[r][1] + bias);
        rv.z = gelu_f(acc[r][2] + bias);
        rv.w = gelu_f(acc[r][3] + bias);
        *(float4*)&B_X(oo, tx * 4) = rv;
    }

    float4 wpre[4];
    #pragma unroll
    for (int u = 0; u < 4; u++) {
        int l = tid + 256 * u;
        int o = l >> 4, j = (l & 15) * 4;
        wpre[u] = *(const float4*)(w1 + (size_t)o * 64 + j);
    }
    __syncthreads();

    float o3[3][4];
    #pragma unroll
    for (int cc = 0; cc < 3; cc++)
        #pragma unroll
        for (int c = 0; c < 4; c++) o3[cc][c] = 0.f;

    for (int oc = 0; oc < 4; oc++) {
        #pragma unroll
        for (int u = 0; u < 4; u++) {
            int l = tid + 256 * u;
            int o = l >> 4, j = (l & 15) * 4;
            B_W(j, o) = wpre[u].x; B_W(j + 1, o) = wpre[u].y;
            B_W(j + 2, o) = wpre[u].z; B_W(j + 3, o) = wpre[u].w;
        }
        __syncthreads();
        if (oc < 3) {
            #pragma unroll
            for (int u = 0; u < 4; u++) {
                int l = tid + 256 * u;
                int o = l >> 4, j = (l & 15) * 4;
                wpre[u] = *(const float4*)(w1 + (size_t)((oc + 1) * 64 + o) * 64 + j);
            }
        }

        float hacc[4][4];
        #pragma unroll
        for (int r = 0; r < 4; r++) {
            float bb = b1[oc * 64 + ty * 4 + r];
            #pragma unroll
            for (int c = 0; c < 4; c++) hacc[r][c] = bb;
        }
        #pragma unroll
        for (int i = 0; i < 64; i++) {
            float4 xv = *(const float4*)&B_X(i, tx * 4);
            float4 wv = *(const float4*)&B_W(i, ty * 4);
            hacc[0][0] += wv.x * xv.x; hacc[0][1] += wv.x * xv.y;
            hacc[0][2] += wv.x * xv.z; hacc[0][3] += wv.x * xv.w;
            hacc[1][0] += wv.y * xv.x; hacc[1][1] += wv.y * xv.y;
            hacc[1][2] += wv.y * xv.z; hacc[1][3] += wv.y * xv.w;
            hacc[2][0] += wv.z * xv.x; hacc[2][1] += wv.z * xv.y;
            hacc[2][2] += wv.z * xv.z; hacc[2][3] += wv.z * xv.w;
            hacc[3][0] += wv.w * xv.x; hacc[3][1] += wv.w * xv.y;
            hacc[3][2] += wv.w * xv.z; hacc[3][3] += wv.w * xv.w;
        }
        #pragma unroll
        for (int r = 0; r < 4; r++) {
            int o = oc * 64 + ty * 4 + r;
            float w20 = w2[o], w21 = w2[256 + o], w22 = w2[512 + o];
            #pragma unroll
            for (int c = 0; c < 4; c++) {
                float hh = gelu_f(hacc[r][c]);
                o3[0][c] += hh * w20;
                o3[1][c] += hh * w21;
                o3[2][c] += hh * w22;
            }
        }
        __syncthreads();
    }

    #pragma unroll
    for (int c = 0; c < 4; c++) {
        int p = tx * 4 + c;
        B_R(ty, p * 3 + 0) = o3[0][c];
        B_R(ty, p * 3 + 1) = o3[1][c];
        B_R(ty, p * 3 + 2) = o3[2][c];
    }
    __syncthreads();
    if (tid < 192) {
        int p = tid / 3, cc = tid % 3;
        float s = b2[cc];
        #pragma unroll
        for (int t = 0; t < 16; t++) s += B_R(t, p * 3 + cc);
        out[((size_t)b * HW + p0 + p) * 3 + cc] = s;
    }
    #undef A_XS
    #undef A_WS
    #undef A_ZS
    #undef A_TW
    #undef B_X
    #undef B_W
    #undef B_R
}

// ---------------- 2x2 mean pool: float2 out per thread, float4 loads ---------
__global__ void k_pool(const float* __restrict__ in, int total, int C, int Ct, int coff,
                       int H, int W, float* __restrict__ out) {
    int idx = blockIdx.x * blockDim.x + threadIdx.x;
    if (idx >= total) return;
    int Ho = H / 2, Wo = W / 2;
    int Wo2 = Wo >> 1;
    int wo2 = idx % Wo2;
    int ho  = (idx / Wo2) % Ho;
    int c   = (idx / (Wo2 * Ho)) % C;
    int b   = idx / (Wo2 * Ho * C);
    const float* p = in + ((size_t)(b * Ct + coff + c) * H + 2 * ho) * W + 4 * wo2;
    float4 a  = *(const float4*)p;
    float4 b4 = *(const float4*)(p + W);
    float2 o2 = make_float2(0.25f * (a.x + a.y + b4.x + b4.y),
                            0.25f * (a.z + a.w + b4.z + b4.w));
    *(float2*)(out + (((size_t)(b * C + c) * Ho + ho) * Wo) + 2 * wo2) = o2;
}

// ------- bilinear 2x upsample: one thread = one 2x2 output quad --------------
__global__ void k_up(const float* __restrict__ in, int total, int C, int H, int W,
                     float* __restrict__ dst, int Ct, int coff) {
    int idx = blockIdx.x * blockDim.x + threadIdx.x;
    if (idx >= total) return;
    int wq = idx % W;
    int hq = (idx / W) % H;
    int c  = (idx / (W * H)) % C;
    int b  = idx / (W * H * C);

    const float* base = in + (size_t)(b * C + c) * H * W;
    int hm = (hq > 0) ? hq - 1 : 0;
    int hp = (hq < H - 1) ? hq + 1 : H - 1;
    int wm = (wq > 0) ? wq - 1 : 0;
    int wp = (wq < W - 1) ? wq + 1 : W - 1;

    float v00 = base[(size_t)hm * W + wm], v01 = base[(size_t)hm * W + wq], v02 = base[(size_t)hm * W + wp];
    float v10 = base[(size_t)hq * W + wm], v11 = base[(size_t)hq * W + wq], v12 = base[(size_t)hq * W + wp];
    float v20 = base[(size_t)hp * W + wm], v21 = base[(size_t)hp * W + wq], v22 = base[(size_t)hp * W + wp];

    float he0 = 0.25f * v00 + 0.75f * v01, ho0 = 0.75f * v01 + 0.25f * v02;
    float he1 = 0.25f * v10 + 0.75f * v11, ho1 = 0.75f * v11 + 0.25f * v12;
    float he2 = 0.25f * v20 + 0.75f * v21, ho2 = 0.75f * v21 + 0.25f * v22;

    int Ho = 2 * H, Wo = 2 * W;
    float* dp = dst + ((size_t)(b * Ct + coff + c) * Ho + 2 * hq) * Wo + 2 * wq;
    *(float2*)dp        = make_float2(0.25f * he0 + 0.75f * he1, 0.25f * ho0 + 0.75f * ho1);
    *(float2*)(dp + Wo) = make_float2(0.75f * he1 + 0.25f * he2, 0.75f * ho1 + 0.25f * ho2);
}

// =============================================================================
static inline int grid_of(int total) { return (total + 255) / 256; }

static void spectral_front(const float* xin, int Ci, int Co, int H, int m1,
                           const float* w1, const float* w2,
                           const float* twW, const float* twH) {
    const int W = H, m2 = m1, m1t2 = 2 * m1;
    int BC = BSZ * Ci;
    k_fwd_w<<<BC * H / 32, 256>>>(xin, H, W, m2, twW, BC);
    int nparts = (H >= 256) ? 4 : (H >= 128) ? 2 : 1;
    dim3 hg(BC * m2 / 16, nparts);
    k_fwd_h<<<hg, 256>>>(H, H / nparts, BC * m2, m1, m2, twH);
    dim3 mg(BSZ * m1t2, 2);
    k_mix<<<mg, 256>>>(Ci, Co, m1, m2, nparts, w1, w2);
    int ny = (H >= 128) ? 4 : 2;
    dim3 ig(BSZ * Co, ny);
    k_inv_h<<<ig, 256>>>(H, m1, m2, twH, 1.0f / (float)(H * W), ny);
}

static void spectral_block(const float* xin, int Ci, int Co, int H, int m1,
                           const float* w1, const float* w2,
                           const float* cw, const float* cb,
                           const float* twW, const float* twH,
                           float* out, int Ct, int coff) {
    const int W = H, m2 = m1;
    spectral_front(xin, Ci, Co, H, m1, w1, w2, twW, twH);
    dim3 fg(BSZ * H * W / 64, (Co + 63) / 64);
    k_fuse<<<fg, 256>>>(xin, Ci, Co, H, W, m2, twW, cw, cb, out, Ct, coff);
}

extern "C" void kernel_launch(void* const* d_in, const int* in_sizes, int n_in,
                              void* d_out, int out_size) {
    const float* x      = (const float*)d_in[0];
    const float* fcin_w = (const float*)d_in[1];
    const float* fcin_b = (const float*)d_in[2];
    const float* sc1_w1 = (const float*)d_in[3];
    const float* sc1_w2 = (const float*)d_in[4];
    const float* c1_w   = (const float*)d_in[5];
    const float* c1_b   = (const float*)d_in[6];
    const float* sc2_w1 = (const float*)d_in[7];
    const float* sc2_w2 = (const float*)d_in[8];
    const float* c2_w   = (const float*)d_in[9];
    const float* c2_b   = (const float*)d_in[10];
    const float* scb_w1 = (const float*)d_in[11];
    const float* scb_w2 = (const float*)d_in[12];
    const float* cb_w   = (const float*)d_in[13];
    const float* cb_b   = (const float*)d_in[14];
    const float* su2_w1 = (const float*)d_in[15];
    const float* su2_w2 = (const float*)d_in[16];
    const float* u2_w   = (const float*)d_in[17];
    const float* u2_b   = (const float*)d_in[18];
    const float* su1_w1 = (const float*)d_in[19];
    const float* su1_w2 = (const float*)d_in[20];
    const float* u1_w   = (const float*)d_in[21];
    const float* u1_b   = (const float*)d_in[22];
    const float* fc1_w  = (const float*)d_in[23];
    const float* fc1_b  = (const float*)d_in[24];
    const float* fc2_w  = (const float*)d_in[25];
    const float* fc2_b  = (const float*)d_in[26];

    float *p_v, *p_x1d, *p_x2d, *p_xb, *p_x2c, *p_x2o, *p_x1c, *p_tw;
    cudaGetSymbolAddress((void**)&p_v,   g_v);
    cudaGetSymbolAddress((void**)&p_x1d, g_x1d);
    cudaGetSymbolAddress((void**)&p_x2d, g_x2d);
    cudaGetSymbolAddress((void**)&p_xb,  g_xb);
    cudaGetSymbolAddress((void**)&p_x2c, g_x2c);
    cudaGetSymbolAddress((void**)&p_x2o, g_x2o);
    cudaGetSymbolAddress((void**)&p_x1c, g_x1c);
    cudaGetSymbolAddress((void**)&p_tw,  g_tw);

    const float* tw_W0 = p_tw + 2 * TW0;
    const float* tw_H0 = p_tw + 2 * TH0;
    const float* tw_W1 = p_tw + 2 * TW1;
    const float* tw_H1 = p_tw + 2 * TH1;
    const float* tw_W2 = p_tw + 2 * TW2;
    const float* tw_H2 = p_tw + 2 * TH2;

    k_init_tw<<<32, 256>>>();

    // lift 6 -> 64 (tiled; x read once)
    k_lift<<<BSZ * 1024, 256>>>(x, fcin_w, fcin_b);

    // encoder level 1: 64 -> 64 @ 256 ; x1 written directly into x1c[96:160]
    spectral_block(p_v, 64, 64, 256, 12, sc1_w1, sc1_w2, c1_w, c1_b, tw_W0, tw_H0,
                   p_x1c, 160, 96);
    {
        int t = BSZ * 64 * 128 * 64;
        k_pool<<<grid_of(t), 256>>>(p_x1c, t, 64, 160, 96, 256, 256, p_x1d);
    }

    // encoder level 2: 64 -> 96 @ 128 ; x2 written into x2c[128:224]
    spectral_block(p_x1d, 64, 96, 128, 8, sc2_w1, sc2_w2, c2_w, c2_b, tw_W1, tw_H1,
                   p_x2c, 224, 128);
    {
        int t = BSZ * 96 * 64 * 32;
        k_pool<<<grid_of(t), 256>>>(p_x2c, t, 96, 224, 128, 128, 128, p_x2d);
    }

    // bottleneck: 96 -> 128 @ 64
    spectral_block(p_x2d, 96, 128, 64, 4, scb_w1, scb_w2, cb_w, cb_b, tw_W2, tw_H2,
                   p_xb, 128, 0);

    // up(xb) -> x2c[0:128]
    {
        int t = BSZ * 128 * 64 * 64;
        k_up<<<grid_of(t), 256>>>(p_xb, t, 128, 64, 64, p_x2c, 224, 0);
    }

    // decoder level 2: 224 -> 96 @ 128
    spectral_block(p_x2c, 224, 96, 128, 8, su2_w1, su2_w2, u2_w, u2_b, tw_W1, tw_H1,
                   p_x2o, 96, 0);

    // up(x2o) -> x1c[0:96]
    {
        int t = BSZ * 96 * 128 * 128;
        k_up<<<grid_of(t), 256>>>(p_x2o, t, 96, 128, 128, p_x1c, 160, 0);
    }

    // decoder level 1 + head, fused: 160 -> 64 @ 256 -> fc1/gelu/fc2 -> out
    spectral_front(p_x1c, 160, 64, 256, 12, su1_w1, su1_w2, tw_W0, tw_H0);
    k_fuse_head<<<BSZ * 1024, 256>>>(p_x1c, 160, tw_W0, u1_w, u1_b,
                                     fc1_w, fc1_b, fc2_w, fc2_b, (float*)d_out);
}

// round 17
// speedup vs baseline: 1.0196x; 1.0196x over previous
#include <cuda_runtime.h>
#include <math.h>

#define BSZ 4

// ---------------- scratch (device globals; no allocations allowed) ----------
__device__ float g_v  [16777216];   // [4,64,256,256]
__device__ float g_x1d[ 4194304];   // [4,64,128,128]
__device__ float g_x2d[ 1572864];   // [4,96,64,64]
__device__ float g_xb [ 2097152];   // [4,128,64,64]
__device__ float g_x2c[14680064];   // [4,224,128,128] (x2 at coff 128)
__device__ float g_x2o[ 6291456];   // [4,96,128,128]
__device__ float g_x1c[41943040];   // [4,160,256,256] (x1 at coff 96)

__device__ float g_XW [ 3932160];   // transposed: [H][BC*m2c]
__device__ float g_XF [  368640];   // partial sums, K-part 0
__device__ float g_XF1[  368640];   // K-part 1
__device__ float g_OF [  368640];   // [B,Co,2m1,m2] complex
__device__ float g_Z  [ 1572864];   // [B,Co,H,m2] complex (scaled)
__device__ float g_tw [   26112];   // twiddle tables (complex interleaved)

#define TW0 0
#define TH0 3072
#define TW1 9216
#define TH1 10240
#define TW2 12288
#define TH2 12544

__device__ __forceinline__ float gelu_f(float x) {
    return 0.5f * x * (1.0f + erff(x * 0.70710678118654752f));
}

// ---------------- twiddle init (float sincospif: exact pi scaling) -----------
__global__ void k_init_tw() {
    const int cfg[3][5] = {{256,12,12,TW0,TH0},{128,8,8,TW1,TH1},{64,4,4,TW2,TH2}};
    int tid = blockIdx.x * blockDim.x + threadIdx.x;
    int nth = gridDim.x * blockDim.x;
    for (int c = 0; c < 3; c++) {
        int H = cfg[c][0], m1 = cfg[c][1], m2 = cfg[c][2];
        int offW = cfg[c][3], offH = cfg[c][4];
        int nW = H * m2;
        for (int e = tid; e < nW; e += nth) {
            int w = e / m2, kw = e % m2;
            int p = (w * kw) % H;
            float s, co;
            sincospif(2.0f * (float)p / (float)H, &s, &co);
            g_tw[(offW + e) * 2]     = co;
            g_tw[(offW + e) * 2 + 1] = -s;
        }
        int m1t2 = 2 * m1;
        int nH = H * m1t2;
        for (int e = tid; e < nH; e += nth) {
            int h = e / m1t2, j = e % m1t2;
            int kh = (j < m1) ? j : (H - 2 * m1 + j);
            int p = (kh * h) % H;
            float s, co;
            sincospif(2.0f * (float)p / (float)H, &s, &co);
            g_tw[(offH + e) * 2]     = co;
            g_tw[(offH + e) * 2 + 1] = -s;
        }
    }
}

// ---------------- lift: tiled 64px x 64c -------------------------------------
__global__ void k_lift(const float* __restrict__ x, const float* __restrict__ w,
                       const float* __restrict__ bb) {
    __shared__ float xs6[64][8];
    __shared__ float ws6[64][8];
    const int HW = 256 * 256;
    int b  = blockIdx.x >> 10;
    int p0 = (blockIdx.x & 1023) << 6;
    int tid = threadIdx.x;

    const float* xp = x + ((size_t)b * HW + p0) * 6;
    for (int l = tid; l < 384; l += 256) xs6[l / 6][l % 6] = xp[l];
    for (int l = tid; l < 384; l += 256) ws6[l / 6][l % 6] = w[l];
    __syncthreads();

    int ty = tid >> 4, tx = tid & 15;
    #pragma unroll
    for (int cr = 0; cr < 4; cr++) {
        int c = ty * 4 + cr;
        float bias = bb[c];
        float res[4];
        #pragma unroll
        for (int pc = 0; pc < 4; pc++) {
            int p = tx * 4 + pc;
            float acc = bias;
            #pragma unroll
            for (int k = 0; k < 6; k++) acc += ws6[c][k] * xs6[p][k];
            res[pc] = acc;
        }
        *(float4*)(g_v + (size_t)(b * 64 + c) * HW + p0 + tx * 4) =
            make_float4(res[0], res[1], res[2], res[3]);
    }
}

// ------- fwd DFT along W with real-input symmetry ----------------------------
__global__ void k_fwd_w(const float* __restrict__ xin, int H, int W, int m2,
                        const float* __restrict__ tw, int BC) {
    __shared__ float raw[32][260];
    __shared__ float tws[129][25];
    int m2c = 2 * m2;
    int Wh = W >> 1;
    int r0 = blockIdx.x * 32;
    int tid = threadIdx.x;
    int row_l = tid >> 3;
    int kc0 = tid & 7;
    bool odd = (kc0 & 1);
    bool v1 = (kc0 + 8 < m2c), v2 = (kc0 + 16 < m2c);

    int nf4 = W >> 2;
    for (int l = tid; l < 32 * nf4; l += 256) {
        int r = l / nf4, q = (l % nf4) * 4;
        *(float4*)&raw[r][q] = *(const float4*)(xin + (size_t)(r0 + r) * W + q);
    }
    for (int l = tid; l < (Wh + 1) * m2c; l += 256) {
        int w = l / m2c, kc = l % m2c;
        tws[w][kc] = tw[(size_t)w * m2c + kc];
    }
    __syncthreads();

    for (int l = tid; l < 32 * (Wh - 1); l += 256) {
        int r = l / (Wh - 1), w = 1 + l % (Wh - 1);
        float a = raw[r][w], bv = raw[r][W - w];
        raw[r][w]     = a + bv;
        raw[r][W - w] = a - bv;
    }
    __syncthreads();

    float a0, a1 = 0.f, a2 = 0.f;
    {
        float x0 = raw[row_l][0], xh = raw[row_l][Wh];
        a0 = x0 * tws[0][kc0] + xh * tws[Wh][kc0];
        if (v1) a1 = x0 * tws[0][kc0 + 8]  + xh * tws[Wh][kc0 + 8];
        if (v2) a2 = x0 * tws[0][kc0 + 16] + xh * tws[Wh][kc0 + 16];
    }
    const float* rrow = raw[row_l];
    #pragma unroll 4
    for (int w = 1; w < Wh; w++) {
        float xv = rrow[odd ? (W - w) : w];
        a0 += xv * tws[w][kc0];
        if (v1) a1 += xv * tws[w][kc0 + 8];
        if (v2) a2 += xv * tws[w][kc0 + 16];
    }
    int r = r0 + row_l;
    int bc = r / H, h = r - bc * H;
    size_t base = ((size_t)h * BC + bc) * m2c;
    g_XW[base + kc0] = a0;
    if (v1) g_XW[base + kc0 + 8]  = a1;
    if (v2) g_XW[base + kc0 + 16] = a2;
}

// ------- fwd DFT along H: split-K over blockIdx.y (2 parts for H>=128) -------
__global__ void k_fwd_h(int H, int H2, int BCm2, int m1, int m2,
                        const float* __restrict__ tw) {
    __shared__ float xs[64][32];
    __shared__ float tws[64][48];
    int m1t2 = 2 * m1;
    int cc0 = blockIdx.x * 16;
    int hy  = blockIdx.y;
    int hbeg = hy * H2, hend = hbeg + H2;
    int tid = threadIdx.x;
    int cl = tid & 15;
    int g  = tid >> 4;
    bool v0 = (g < m1t2);
    bool v1 = (g + 16 < m1t2);
    float ar0 = 0.f, ai0 = 0.f, ar1 = 0.f, ai1 = 0.f;
    int N2 = BCm2 * 2;

    for (int h0 = hbeg; h0 < hend; h0 += 64) {
        for (int l = tid; l < 64 * 8; l += 256) {
            int hh = l >> 3, c4 = (l & 7) * 4;
            *(float4*)&xs[hh][c4] =
                *(const float4*)(g_XW + (size_t)(h0 + hh) * N2 + cc0 * 2 + c4);
        }
        for (int l = tid; l < 64 * m1t2 * 2; l += 256) {
            int hh = l / (m1t2 * 2), c = l % (m1t2 * 2);
            tws[hh][c] = tw[(size_t)(h0 + hh) * m1t2 * 2 + c];
        }
        __syncthreads();
        #pragma unroll 4
        for (int hh = 0; hh < 64; hh++) {
            float2 xv = *(const float2*)&xs[hh][2 * cl];
            if (v0) {
                float tr = tws[hh][2 * g], ti = tws[hh][2 * g + 1];
                ar0 += xv.x * tr - xv.y * ti;
                ai0 += xv.x * ti + xv.y * tr;
            }
            if (v1) {
                float tr1 = tws[hh][2 * (g + 16)], ti1 = tws[hh][2 * (g + 16) + 1];
                ar1 += xv.x * tr1 - xv.y * ti1;
                ai1 += xv.x * ti1 + xv.y * tr1;
            }
        }
        __syncthreads();
    }
    float* dst = (hy == 0) ? g_XF : g_XF1;
    int cc = cc0 + cl, bc = cc / m2, kw = cc % m2;
    if (v0) {
        size_t oo = (((size_t)bc * m1t2 + g) * m2 + kw) * 2;
        dst[oo] = ar0; dst[oo + 1] = ai0;
    }
    if (v1) {
        size_t oo = (((size_t)bc * m1t2 + g + 16) * m2 + kw) * 2;
        dst[oo] = ar1; dst[oo + 1] = ai1;
    }
}

// ------- per-mode channel mix; sums split-K partials during staging ----------
__global__ void k_mix(int Ci, int Co, int m1, int m2, int nparts,
                      const float* __restrict__ w1, const float* __restrict__ w2) {
    __shared__ float xf_s[3840];
    int m1t2 = 2 * m1, m2c = 2 * m2;
    int kk = blockIdx.x % m1t2;
    int b  = blockIdx.x / m1t2;
    int oy = blockIdx.y;
    int tid = threadIdx.x;

    for (int l = tid; l < Ci * m2c; l += 256) {
        int i = l / m2c, kc = l % m2c;
        size_t gi = (((size_t)(b * Ci + i) * m1t2 + kk) * m2) * 2 + kc;
        float v = g_XF[gi];
        if (nparts == 2) v += g_XF1[gi];
        xf_s[l] = v;
    }
    __syncthreads();

    int kkr = (kk < m1) ? kk : kk - m1;
    const float* wsel = (kk < m1) ? w1 : w2;
    int wstride = Co * m1 * m2 * 2;
    int nout = Co * m2;
    int half = nout >> 1;
    int e_begin = oy * half;
    int e_end   = e_begin + half;
    for (int e0 = e_begin + tid; e0 < e_end; e0 += 1024) {
        float orr[4] = {0,0,0,0}, oii[4] = {0,0,0,0};
        int xoff[4], woff[4]; bool val[4];
        #pragma unroll
        for (int u = 0; u < 4; u++) {
            int e = e0 + 256 * u;
            val[u] = (e < e_end);
            int kw = val[u] ? e % m2 : 0;
            int o  = val[u] ? e / m2 : 0;
            xoff[u] = 2 * kw;
            woff[u] = ((o * m1 + kkr) * m2 + kw) * 2;
        }
        for (int i = 0; i < Ci; i++) {
            const float* wrow = wsel + (size_t)i * wstride;
            const float* xrow = xf_s + i * m2c;
            #pragma unroll
            for (int u = 0; u < 4; u++) {
                float xr = xrow[xoff[u]], xi = xrow[xoff[u] + 1];
                float wr = wrow[woff[u]], wi = wrow[woff[u] + 1];
                orr[u] += xr * wr - xi * wi;
                oii[u] += xr * wi + xi * wr;
            }
        }
        #pragma unroll
        for (int u = 0; u < 4; u++) {
            if (val[u]) {
                int e = e0 + 256 * u;
                int kw = e % m2, o = e / m2;
                size_t oo = (((size_t)(b * Co + o) * m1t2 + kk) * m2 + kw) * 2;
                g_OF[oo] = orr[u]; g_OF[oo + 1] = oii[u];
            }
        }
    }
}

// ------- inverse DFT along H; H rows split over blockIdx.y (2 parts) ---------
__global__ void k_inv_h(int H, int m1, int m2, const float* __restrict__ tw,
                        float invHW) {
    __shared__ float of_s[1152];
    int bo = blockIdx.x;
    int hy = blockIdx.y;
    int tid = threadIdx.x;
    int m1t2 = 2 * m1;
    int nload = m1t2 * m2 * 2;
    const float* src = g_OF + (size_t)bo * nload;
    for (int l = tid; l < nload; l += 256) of_s[l] = src[l];
    __syncthreads();

    int nout = H * m2;
    int nh = nout >> 1;
    int e_begin = hy * nh;
    int e_end = e_begin + nh;
    for (int e = e_begin + tid; e < e_end; e += 512) {
        int e2 = e + 256;
        bool v2 = (e2 < e_end);
        int kw0 = e % m2, h0 = e / m2;
        int kw1 = v2 ? e2 % m2 : 0, h1 = v2 ? e2 / m2 : 0;
        float zr0 = 0.f, zi0 = 0.f, zr1 = 0.f, zi1 = 0.f;
        for (int kk = 0; kk < m1t2; kk++) {
            float tr0 = tw[(h0 * m1t2 + kk) * 2], ti0 = tw[(h0 * m1t2 + kk) * 2 + 1];
            float fr0 = of_s[(kk * m2 + kw0) * 2], fi0 = of_s[(kk * m2 + kw0) * 2 + 1];
            zr0 += fr0 * tr0 + fi0 * ti0;
            zi0 += fi0 * tr0 - fr0 * ti0;
            float tr1 = tw[(h1 * m1t2 + kk) * 2], ti1 = tw[(h1 * m1t2 + kk) * 2 + 1];
            float fr1 = of_s[(kk * m2 + kw1) * 2], fi1 = of_s[(kk * m2 + kw1) * 2 + 1];
            zr1 += fr1 * tr1 + fi1 * ti1;
            zi1 += fi1 * tr1 - fr1 * ti1;
        }
        size_t oo = ((size_t)bo * nout + e) * 2;
        g_Z[oo] = zr0 * invHW; g_Z[oo + 1] = zi0 * invHW;
        if (v2) {
            oo = ((size_t)bo * nout + e2) * 2;
            g_Z[oo] = zr1 * invHW; g_Z[oo + 1] = zi1 * invHW;
        }
    }
}

// ------- fused GEMM: ping-pong smem double buffering, one sync per K-chunk ---
__global__ void k_fuse(const float* __restrict__ xin, int Ci, int Co,
                       int H, int W, int m2, const float* __restrict__ tw,
                       const float* __restrict__ cw, const float* __restrict__ cb,
                       float* __restrict__ out, int Ct, int coff) {
    __shared__ float xs[2][32][68];
    __shared__ float wst[2][32][68];
    __shared__ float zst[24][68];
    __shared__ float twst[24][68];

    const int HW = H * W;
    int tilesPerImg = HW >> 6;
    int b  = blockIdx.x / tilesPerImg;
    int p0 = (blockIdx.x % tilesPerImg) << 6;
    int ob = blockIdx.y << 6;
    int h  = p0 / W, w0 = p0 % W;
    int tid = threadIdx.x;
    int ty = tid >> 4, tx = tid & 15;
    int m2c = 2 * m2;

    int l0 = tid, l1 = tid + 256;
    int xi0 = l0 >> 4, xq0 = (l0 & 15) * 4;
    int xi1 = l1 >> 4, xq1 = (l1 & 15) * 4;
    int wo0 = l0 >> 3, wj0 = (l0 & 7) * 4;
    int wo1 = l1 >> 3, wj1 = (l1 & 7) * 4;
    int woo0 = ob + wo0, woo1 = ob + wo1;
    const float* wrow0 = cw + (size_t)woo0 * Ci;
    const float* wrow1 = cw + (size_t)woo1 * Ci;
    bool wv0 = (woo0 < Co), wv1 = (woo1 < Co);

    for (int l = tid; l < m2c * 64; l += 256) {
        int r = l >> 6, o = l & 63;
        int oo = ob + o;
        float v = (oo < Co) ? g_Z[(((size_t)(b * Co + oo) * H + h) * m2) * 2 + r] : 0.f;
        zst[r][o] = (r >= 2) ? 2.0f * v : v;
    }
    for (int l = tid; l < m2c * 64; l += 256) {
        int r = l >> 6, p = l & 63;
        twst[r][p] = tw[(size_t)(w0 + p) * m2c + r];
    }
    {
        float4 xa = *(const float4*)(xin + (size_t)(b * Ci + xi0) * HW + p0 + xq0);
        float4 xb = *(const float4*)(xin + (size_t)(b * Ci + xi1) * HW + p0 + xq1);
        float4 wa = wv0 ? *(const float4*)(wrow0 + wj0) : make_float4(0.f,0.f,0.f,0.f);
        float4 wb = wv1 ? *(const float4*)(wrow1 + wj1) : make_float4(0.f,0.f,0.f,0.f);
        *(float4*)&xs[0][xi0][xq0] = xa;
        *(float4*)&xs[0][xi1][xq1] = xb;
        wst[0][wj0][wo0] = wa.x; wst[0][wj0+1][wo0] = wa.y;
        wst[0][wj0+2][wo0] = wa.z; wst[0][wj0+3][wo0] = wa.w;
        wst[0][wj1][wo1] = wb.x; wst[0][wj1+1][wo1] = wb.y;
        wst[0][wj1+2][wo1] = wb.z; wst[0][wj1+3][wo1] = wb.w;
    }
    __syncthreads();

    float acc[4][4];
    #pragma unroll
    for (int r = 0; r < 4; r++)
        #pragma unroll
        for (int c = 0; c < 4; c++) acc[r][c] = 0.f;
    for (int r = 0; r < m2c; r++) {
        float4 zv = *(const float4*)&zst[r][ty * 4];
        float4 tv = *(const float4*)&twst[r][tx * 4];
        acc[0][0] += zv.x * tv.x; acc[0][1] += zv.x * tv.y;
        acc[0][2] += zv.x * tv.z; acc[0][3] += zv.x * tv.w;
        acc[1][0] += zv.y * tv.x; acc[1][1] += zv.y * tv.y;
        acc[1][2] += zv.y * tv.z; acc[1][3] += zv.y * tv.w;
        acc[2][0] += zv.z * tv.x; acc[2][1] += zv.z * tv.y;
        acc[2][2] += zv.z * tv.z; acc[2][3] += zv.z * tv.w;
        acc[3][0] += zv.w * tv.x; acc[3][1] += zv.w * tv.y;
        acc[3][2] += zv.w * tv.z; acc[3][3] += zv.w * tv.w;
    }

    int nchunks = Ci >> 5;
    for (int k = 0; k < nchunks; k++) {
        int cur = k & 1;
        bool more = (k + 1 < nchunks);
        float4 xa, xb, wa, wb;
        if (more) {
            int cin = (k + 1) << 5;
            xa = *(const float4*)(xin + (size_t)(b * Ci + cin + xi0) * HW + p0 + xq0);
            xb = *(const float4*)(xin + (size_t)(b * Ci + cin + xi1) * HW + p0 + xq1);
            wa = wv0 ? *(const float4*)(wrow0 + cin + wj0) : make_float4(0.f,0.f,0.f,0.f);
            wb = wv1 ? *(const float4*)(wrow1 + cin + wj1) : make_float4(0.f,0.f,0.f,0.f);
        }
        #pragma unroll
        for (int i = 0; i < 32; i++) {
            float4 xv = *(const float4*)&xs[cur][i][tx * 4];
            float4 wv = *(const float4*)&wst[cur][i][ty * 4];
            acc[0][0] += wv.x * xv.x; acc[0][1] += wv.x * xv.y;
            acc[0][2] += wv.x * xv.z; acc[0][3] += wv.x * xv.w;
            acc[1][0] += wv.y * xv.x; acc[1][1] += wv.y * xv.y;
            acc[1][2] += wv.y * xv.z; acc[1][3] += wv.y * xv.w;
            acc[2][0] += wv.z * xv.x; acc[2][1] += wv.z * xv.y;
            acc[2][2] += wv.z * xv.z; acc[2][3] += wv.z * xv.w;
            acc[3][0] += wv.w * xv.x; acc[3][1] += wv.w * xv.y;
            acc[3][2] += wv.w * xv.z; acc[3][3] += wv.w * xv.w;
        }
        if (more) {
            int nb = cur ^ 1;
            *(float4*)&xs[nb][xi0][xq0] = xa;
            *(float4*)&xs[nb][xi1][xq1] = xb;
            wst[nb][wj0][wo0] = wa.x; wst[nb][wj0+1][wo0] = wa.y;
            wst[nb][wj0+2][wo0] = wa.z; wst[nb][wj0+3][wo0] = wa.w;
            wst[nb][wj1][wo1] = wb.x; wst[nb][wj1+1][wo1] = wb.y;
            wst[nb][wj1+2][wo1] = wb.z; wst[nb][wj1+3][wo1] = wb.w;
            __syncthreads();
        }
    }

    #pragma unroll
    for (int r = 0; r < 4; r++) {
        int oo = ob + ty * 4 + r;
        if (oo >= Co) continue;
        float bias = cb[oo];
        float res[4];
        #pragma unroll
        for (int c = 0; c < 4; c++) res[c] = gelu_f(acc[r][c] + bias);
        *(float4*)(out + (size_t)(b * Ct + coff + oo) * HW + p0 + tx * 4) =
            make_float4(res[0], res[1], res[2], res[3]);
    }
}

// ------- FINAL LAYER: fuse(su1) + head merged; x1o never touches gmem --------
__global__ void k_fuse_head(const float* __restrict__ xin, int Ci,
                            const float* __restrict__ tw,
                            const float* __restrict__ cw, const float* __restrict__ cb,
                            const float* __restrict__ w1, const float* __restrict__ b1,
                            const float* __restrict__ w2, const float* __restrict__ b2,
                            float* __restrict__ out) {
    __shared__ float S[11968];
    #define A_XS(bf,i,q)  S[(bf) * 2176 + (i) * 68 + (q)]
    #define A_WS(bf,i,o)  S[4352 + (bf) * 2176 + (i) * 68 + (o)]
    #define A_ZS(r,o)     S[8704 + (r) * 68 + (o)]
    #define A_TW(r,p)     S[10336 + (r) * 68 + (p)]
    #define B_X(i,p)      S[(i) * 68 + (p)]
    #define B_W(i,o)      S[4352 + (i) * 68 + (o)]
    #define B_R(t,l)      S[8704 + (t) * 200 + (l)]

    const int H = 256, m2 = 12, m2c = 24;
    const int HW = 65536;
    int b  = blockIdx.x >> 10;
    int p0 = (blockIdx.x & 1023) << 6;
    int h  = p0 >> 8, w0 = p0 & 255;
    int tid = threadIdx.x;
    int ty = tid >> 4, tx = tid & 15;

    int l0 = tid, l1 = tid + 256;
    int xi0 = l0 >> 4, xq0 = (l0 & 15) * 4;
    int xi1 = l1 >> 4, xq1 = (l1 & 15) * 4;
    int wo0 = l0 >> 3, wj0 = (l0 & 7) * 4;
    int wo1 = l1 >> 3, wj1 = (l1 & 7) * 4;
    const float* wrow0 = cw + (size_t)wo0 * Ci;
    const float* wrow1 = cw + (size_t)wo1 * Ci;

    for (int l = tid; l < m2c * 64; l += 256) {
        int r = l >> 6, o = l & 63;
        float v = g_Z[(((size_t)(b * 64 + o) * H + h) * m2) * 2 + r];
        A_ZS(r, o) = (r >= 2) ? 2.0f * v : v;
    }
    for (int l = tid; l < m2c * 64; l += 256) {
        int r = l >> 6, p = l & 63;
        A_TW(r, p) = tw[(size_t)(w0 + p) * m2c + r];
    }
    {
        float4 xa = *(const float4*)(xin + (size_t)(b * Ci + xi0) * HW + p0 + xq0);
        float4 xb = *(const float4*)(xin + (size_t)(b * Ci + xi1) * HW + p0 + xq1);
        float4 wa = *(const float4*)(wrow0 + wj0);
        float4 wb = *(const float4*)(wrow1 + wj1);
        *(float4*)&A_XS(0, xi0, xq0) = xa;
        *(float4*)&A_XS(0, xi1, xq1) = xb;
        A_WS(0, wj0, wo0) = wa.x; A_WS(0, wj0+1, wo0) = wa.y;
        A_WS(0, wj0+2, wo0) = wa.z; A_WS(0, wj0+3, wo0) = wa.w;
        A_WS(0, wj1, wo1) = wb.x; A_WS(0, wj1+1, wo1) = wb.y;
        A_WS(0, wj1+2, wo1) = wb.z; A_WS(0, wj1+3, wo1) = wb.w;
    }
    __syncthreads();

    float acc[4][4];
    #pragma unroll
    for (int r = 0; r < 4; r++)
        #pragma unroll
        for (int c = 0; c < 4; c++) acc[r][c] = 0.f;
    for (int r = 0; r < m2c; r++) {
        float4 zv = *(const float4*)&A_ZS(r, ty * 4);
        float4 tv = *(const float4*)&A_TW(r, tx * 4);
        acc[0][0] += zv.x * tv.x; acc[0][1] += zv.x * tv.y;
        acc[0][2] += zv.x * tv.z; acc[0][3] += zv.x * tv.w;
        acc[1][0] += zv.y * tv.x; acc[1][1] += zv.y * tv.y;
        acc[1][2] += zv.y * tv.z; acc[1][3] += zv.y * tv.w;
        acc[2][0] += zv.z * tv.x; acc[2][1] += zv.z * tv.y;
        acc[2][2] += zv.z * tv.z; acc[2][3] += zv.z * tv.w;
        acc[3][0] += zv.w * tv.x; acc[3][1] += zv.w * tv.y;
        acc[3][2] += zv.w * tv.z; acc[3][3] += zv.w * tv.w;
    }

    int nchunks = Ci >> 5;
    for (int k = 0; k < nchunks; k++) {
        int cur = k & 1;
        bool more = (k + 1 < nchunks);
        float4 xa, xb, wa, wb;
        if (more) {
            int cin = (k + 1) << 5;
            xa = *(const float4*)(xin + (size_t)(b * Ci + cin + xi0) * HW + p0 + xq0);
            xb = *(const float4*)(xin + (size_t)(b * Ci + cin + xi1) * HW + p0 + xq1);
            wa = *(const float4*)(wrow0 + cin + wj0);
            wb = *(const float4*)(wrow1 + cin + wj1);
        }
        #pragma unroll
        for (int i = 0; i < 32; i++) {
            float4 xv = *(const float4*)&A_XS(cur, i, tx * 4);
            float4 wv = *(const float4*)&A_WS(cur, i, ty * 4);
            acc[0][0] += wv.x * xv.x; acc[0][1] += wv.x * xv.y;
            acc[0][2] += wv.x * xv.z; acc[0][3] += wv.x * xv.w;
            acc[1][0] += wv.y * xv.x; acc[1][1] += wv.y * xv.y;
            acc[1][2] += wv.y * xv.z; acc[1][3] += wv.y * xv.w;
            acc[2][0] += wv.z * xv.x; acc[2][1] += wv.z * xv.y;
            acc[2][2] += wv.z * xv.z; acc[2][3] += wv.z * xv.w;
            acc[3][0] += wv.w * xv.x; acc[3][1] += wv.w * xv.y;
            acc[3][2] += wv.w * xv.z; acc[3][3] += wv.w * xv.w;
        }
        if (more) {
            int nb = cur ^ 1;
            *(float4*)&A_XS(nb, xi0, xq0) = xa;
            *(float4*)&A_XS(nb, xi1, xq1) = xb;
            A_WS(nb, wj0, wo0) = wa.x; A_WS(nb, wj0+1, wo0) = wa.y;
            A_WS(nb, wj0+2, wo0) = wa.z; A_WS(nb, wj0+3, wo0) = wa.w;
            A_WS(nb, wj1, wo1) = wb.x; A_WS(nb, wj1+1, wo1) = wb.y;
            A_WS(nb, wj1+2, wo1) = wb.z; A_WS(nb, wj1+3, wo1) = wb.w;
            __syncthreads();
        }
    }
    __syncthreads();

    #pragma unroll
    for (int r = 0; r < 4; r++) {
        int oo = ty * 4 + r;
        float bias = cb[oo];
        float4 rv;
        rv.x = gelu_f(acc[r][0] + bias);
        rv.y = gelu_f(acc[r][1] + bias);
        rv.z = gelu_f(acc[r][2] + bias);
        rv.w = gelu_f(acc[r][3] + bias);
        *(float4*)&B_X(oo, tx * 4) = rv;
    }

    float4 wpre[4];
    #pragma unroll
    for (int u = 0; u < 4; u++) {
        int l = tid + 256 * u;
        int o = l >> 4, j = (l & 15) * 4;
        wpre[u] = *(const float4*)(w1 + (size_t)o * 64 + j);
    }
    __syncthreads();

    float o3[3][4];
    #pragma unroll
    for (int cc = 0; cc < 3; cc++)
        #pragma unroll
        for (int c = 0; c < 4; c++) o3[cc][c] = 0.f;

    for (int oc = 0; oc < 4; oc++) {
        #pragma unroll
        for (int u = 0; u < 4; u++) {
            int l = tid + 256 * u;
            int o = l >> 4, j = (l & 15) * 4;
            B_W(j, o) = wpre[u].x; B_W(j + 1, o) = wpre[u].y;
            B_W(j + 2, o) = wpre[u].z; B_W(j + 3, o) = wpre[u].w;
        }
        __syncthreads();
        if (oc < 3) {
            #pragma unroll
            for (int u = 0; u < 4; u++) {
                int l = tid + 256 * u;
                int o = l >> 4, j = (l & 15) * 4;
                wpre[u] = *(const float4*)(w1 + (size_t)((oc + 1) * 64 + o) * 64 + j);
            }
        }

        float hacc[4][4];
        #pragma unroll
        for (int r = 0; r < 4; r++) {
            float bb = b1[oc * 64 + ty * 4 + r];
            #pragma unroll
            for (int c = 0; c < 4; c++) hacc[r][c] = bb;
        }
        #pragma unroll
        for (int i = 0; i < 64; i++) {
            float4 xv = *(const float4*)&B_X(i, tx * 4);
            float4 wv = *(const float4*)&B_W(i, ty * 4);
            hacc[0][0] += wv.x * xv.x; hacc[0][1] += wv.x * xv.y;
            hacc[0][2] += wv.x * xv.z; hacc[0][3] += wv.x * xv.w;
            hacc[1][0] += wv.y * xv.x; hacc[1][1] += wv.y * xv.y;
            hacc[1][2] += wv.y * xv.z; hacc[1][3] += wv.y * xv.w;
            hacc[2][0] += wv.z * xv.x; hacc[2][1] += wv.z * xv.y;
            hacc[2][2] += wv.z * xv.z; hacc[2][3] += wv.z * xv.w;
            hacc[3][0] += wv.w * xv.x; hacc[3][1] += wv.w * xv.y;
            hacc[3][2] += wv.w * xv.z; hacc[3][3] += wv.w * xv.w;
        }
        #pragma unroll
        for (int r = 0; r < 4; r++) {
            int o = oc * 64 + ty * 4 + r;
            float w20 = w2[o], w21 = w2[256 + o], w22 = w2[512 + o];
            #pragma unroll
            for (int c = 0; c < 4; c++) {
                float hh = gelu_f(hacc[r][c]);
                o3[0][c] += hh * w20;
                o3[1][c] += hh * w21;
                o3[2][c] += hh * w22;
            }
        }
        __syncthreads();
    }

    #pragma unroll
    for (int c = 0; c < 4; c++) {
        int p = tx * 4 + c;
        B_R(ty, p * 3 + 0) = o3[0][c];
        B_R(ty, p * 3 + 1) = o3[1][c];
        B_R(ty, p * 3 + 2) = o3[2][c];
    }
    __syncthreads();
    if (tid < 192) {
        int p = tid / 3, cc = tid % 3;
        float s = b2[cc];
        #pragma unroll
        for (int t = 0; t < 16; t++) s += B_R(t, p * 3 + cc);
        out[((size_t)b * HW + p0 + p) * 3 + cc] = s;
    }
    #undef A_XS
    #undef A_WS
    #undef A_ZS
    #undef A_TW
    #undef B_X
    #undef B_W
    #undef B_R
}

// ---------------- 2x2 mean pool: float2 out per thread, float4 loads ---------
__global__ void k_pool(const float* __restrict__ in, int total, int C, int Ct, int coff,
                       int H, int W, float* __restrict__ out) {
    int idx = blockIdx.x * blockDim.x + threadIdx.x;
    if (idx >= total) return;
    int Ho = H / 2, Wo = W / 2;
    int Wo2 = Wo >> 1;
    int wo2 = idx % Wo2;
    int ho  = (idx / Wo2) % Ho;
    int c   = (idx / (Wo2 * Ho)) % C;
    int b   = idx / (Wo2 * Ho * C);
    const float* p = in + ((size_t)(b * Ct + coff + c) * H + 2 * ho) * W + 4 * wo2;
    float4 a  = *(const float4*)p;
    float4 b4 = *(const float4*)(p + W);
    float2 o2 = make_float2(0.25f * (a.x + a.y + b4.x + b4.y),
                            0.25f * (a.z + a.w + b4.z + b4.w));
    *(float2*)(out + (((size_t)(b * C + c) * Ho + ho) * Wo) + 2 * wo2) = o2;
}

// ------- bilinear 2x upsample: one thread = one 2x2 output quad --------------
__global__ void k_up(const float* __restrict__ in, int total, int C, int H, int W,
                     float* __restrict__ dst, int Ct, int coff) {
    int idx = blockIdx.x * blockDim.x + threadIdx.x;
    if (idx >= total) return;
    int wq = idx % W;
    int hq = (idx / W) % H;
    int c  = (idx / (W * H)) % C;
    int b  = idx / (W * H * C);

    const float* base = in + (size_t)(b * C + c) * H * W;
    int hm = (hq > 0) ? hq - 1 : 0;
    int hp = (hq < H - 1) ? hq + 1 : H - 1;
    int wm = (wq > 0) ? wq - 1 : 0;
    int wp = (wq < W - 1) ? wq + 1 : W - 1;

    float v00 = base[(size_t)hm * W + wm], v01 = base[(size_t)hm * W + wq], v02 = base[(size_t)hm * W + wp];
    float v10 = base[(size_t)hq * W + wm], v11 = base[(size_t)hq * W + wq], v12 = base[(size_t)hq * W + wp];
    float v20 = base[(size_t)hp * W + wm], v21 = base[(size_t)hp * W + wq], v22 = base[(size_t)hp * W + wp];

    float he0 = 0.25f * v00 + 0.75f * v01, ho0 = 0.75f * v01 + 0.25f * v02;
    float he1 = 0.25f * v10 + 0.75f * v11, ho1 = 0.75f * v11 + 0.25f * v12;
    float he2 = 0.25f * v20 + 0.75f * v21, ho2 = 0.75f * v21 + 0.25f * v22;

    int Ho = 2 * H, Wo = 2 * W;
    float* dp = dst + ((size_t)(b * Ct + coff + c) * Ho + 2 * hq) * Wo + 2 * wq;
    *(float2*)dp        = make_float2(0.25f * he0 + 0.75f * he1, 0.25f * ho0 + 0.75f * ho1);
    *(float2*)(dp + Wo) = make_float2(0.75f * he1 + 0.25f * he2, 0.75f * ho1 + 0.25f * ho2);
}

// =============================================================================
static inline int grid_of(int total) { return (total + 255) / 256; }

static void spectral_front(const float* xin, int Ci, int Co, int H, int m1,
                           const float* w1, const float* w2,
                           const float* twW, const float* twH) {
    const int W = H, m2 = m1, m1t2 = 2 * m1;
    int BC = BSZ * Ci;
    k_fwd_w<<<BC * H / 32, 256>>>(xin, H, W, m2, twW, BC);
    int nparts = (H >= 128) ? 2 : 1;
    dim3 hg(BC * m2 / 16, nparts);
    k_fwd_h<<<hg, 256>>>(H, H / nparts, BC * m2, m1, m2, twH);
    dim3 mg(BSZ * m1t2, 2);
    k_mix<<<mg, 256>>>(Ci, Co, m1, m2, nparts, w1, w2);
    dim3 ig(BSZ * Co, 2);
    k_inv_h<<<ig, 256>>>(H, m1, m2, twH, 1.0f / (float)(H * W));
}

static void spectral_block(const float* xin, int Ci, int Co, int H, int m1,
                           const float* w1, const float* w2,
                           const float* cw, const float* cb,
                           const float* twW, const float* twH,
                           float* out, int Ct, int coff) {
    const int W = H, m2 = m1;
    spectral_front(xin, Ci, Co, H, m1, w1, w2, twW, twH);
    dim3 fg(BSZ * H * W / 64, (Co + 63) / 64);
    k_fuse<<<fg, 256>>>(xin, Ci, Co, H, W, m2, twW, cw, cb, out, Ct, coff);
}

extern "C" void kernel_launch(void* const* d_in, const int* in_sizes, int n_in,
                              void* d_out, int out_size) {
    const float* x      = (const float*)d_in[0];
    const float* fcin_w = (const float*)d_in[1];
    const float* fcin_b = (const float*)d_in[2];
    const float* sc1_w1 = (const float*)d_in[3];
    const float* sc1_w2 = (const float*)d_in[4];
    const float* c1_w   = (const float*)d_in[5];
    const float* c1_b   = (const float*)d_in[6];
    const float* sc2_w1 = (const float*)d_in[7];
    const float* sc2_w2 = (const float*)d_in[8];
    const float* c2_w   = (const float*)d_in[9];
    const float* c2_b   = (const float*)d_in[10];
    const float* scb_w1 = (const float*)d_in[11];
    const float* scb_w2 = (const float*)d_in[12];
    const float* cb_w   = (const float*)d_in[13];
    const float* cb_b   = (const float*)d_in[14];
    const float* su2_w1 = (const float*)d_in[15];
    const float* su2_w2 = (const float*)d_in[16];
    const float* u2_w   = (const float*)d_in[17];
    const float* u2_b   = (const float*)d_in[18];
    const float* su1_w1 = (const float*)d_in[19];
    const float* su1_w2 = (const float*)d_in[20];
    const float* u1_w   = (const float*)d_in[21];
    const float* u1_b   = (const float*)d_in[22];
    const float* fc1_w  = (const float*)d_in[23];
    const float* fc1_b  = (const float*)d_in[24];
    const float* fc2_w  = (const float*)d_in[25];
    const float* fc2_b  = (const float*)d_in[26];

    float *p_v, *p_x1d, *p_x2d, *p_xb, *p_x2c, *p_x2o, *p_x1c, *p_tw;
    cudaGetSymbolAddress((void**)&p_v,   g_v);
    cudaGetSymbolAddress((void**)&p_x1d, g_x1d);
    cudaGetSymbolAddress((void**)&p_x2d, g_x2d);
    cudaGetSymbolAddress((void**)&p_xb,  g_xb);
    cudaGetSymbolAddress((void**)&p_x2c, g_x2c);
    cudaGetSymbolAddress((void**)&p_x2o, g_x2o);
    cudaGetSymbolAddress((void**)&p_x1c, g_x1c);
    cudaGetSymbolAddress((void**)&p_tw,  g_tw);

    const float* tw_W0 = p_tw + 2 * TW0;
    const float* tw_H0 = p_tw + 2 * TH0;
    const float* tw_W1 = p_tw + 2 * TW1;
    const float* tw_H1 = p_tw + 2 * TH1;
    const float* tw_W2 = p_tw + 2 * TW2;
    const float* tw_H2 = p_tw + 2 * TH2;

    k_init_tw<<<32, 256>>>();

    // lift 6 -> 64 (tiled; x read once)
    k_lift<<<BSZ * 1024, 256>>>(x, fcin_w, fcin_b);

    // encoder level 1: 64 -> 64 @ 256 ; x1 written directly into x1c[96:160]
    spectral_block(p_v, 64, 64, 256, 12, sc1_w1, sc1_w2, c1_w, c1_b, tw_W0, tw_H0,
                   p_x1c, 160, 96);
    {
        int t = BSZ * 64 * 128 * 64;
        k_pool<<<grid_of(t), 256>>>(p_x1c, t, 64, 160, 96, 256, 256, p_x1d);
    }

    // encoder level 2: 64 -> 96 @ 128 ; x2 written into x2c[128:224]
    spectral_block(p_x1d, 64, 96, 128, 8, sc2_w1, sc2_w2, c2_w, c2_b, tw_W1, tw_H1,
                   p_x2c, 224, 128);
    {
        int t = BSZ * 96 * 64 * 32;
        k_pool<<<grid_of(t), 256>>>(p_x2c, t, 96, 224, 128, 128, 128, p_x2d);
    }

    // bottleneck: 96 -> 128 @ 64
    spectral_block(p_x2d, 96, 128, 64, 4, scb_w1, scb_w2, cb_w, cb_b, tw_W2, tw_H2,
                   p_xb, 128, 0);

    // up(xb) -> x2c[0:128]
    {
        int t = BSZ * 128 * 64 * 64;
        k_up<<<grid_of(t), 256>>>(p_xb, t, 128, 64, 64, p_x2c, 224, 0);
    }

    // decoder level 2: 224 -> 96 @ 128
    spectral_block(p_x2c, 224, 96, 128, 8, su2_w1, su2_w2, u2_w, u2_b, tw_W1, tw_H1,
                   p_x2o, 96, 0);

    // up(x2o) -> x1c[0:96]
    {
        int t = BSZ * 96 * 128 * 128;
        k_up<<<grid_of(t), 256>>>(p_x2o, t, 96, 128, 128, p_x1c, 160, 0);
    }

    // decoder level 1 + head, fused: 160 -> 64 @ 256 -> fc1/gelu/fc2 -> out
    spectral_front(p_x1c, 160, 64, 256, 12, su1_w1, su1_w2, tw_W0, tw_H0);
    k_fuse_head<<<BSZ * 1024, 256>>>(p_x1c, 160, tw_W0, u1_w, u1_b,
                                     fc1_w, fc1_b, fc2_w, fc2_b, (float*)d_out);
}